// round 14
// baseline (speedup 1.0000x reference)
#include <cuda_runtime.h>

// PercolationQ: per-patch occupancy fraction -> threshold -> mean over patches.
// Pure HBM-bound streaming reduction over three 50 MB fp32 tensors.
//
//   x4 : [3,64,4096,4,4]   patch = 16 floats  (4 lanes)
//   x8 : [3,64,1024,8,8]   patch = 64 floats  (16 lanes)
//   x16: [3,64, 256,16,16] patch = 256 floats (2 warp-iterations)
// Output: [q4(3,64), q8(3,64), q16(3,64)] = 576 floats.
//
// R12 = R9 (best: 5.9 TB/s), balanced. Mode-W grid: 148 blocks x 1024 threads
// (1 CTA/SM, 32 warps) -- validated to remove cross-CTA L1tex contention.
// Each warp owns EXACTLY ONE 32 KB segment (4608 segments; single balanced
// pass, no grid-stride loop). Inner loop is R9's proven issue pattern: 8
// batches of 8 coalesced LDG.128 (512 B per warp-load) into a single v[8]
// buffer, then shfl reduction -- warp-level overlap across 32 warps covers
// the reduce phases (explicit pipelining measured WORSE in R10/R11).
// Integer per-warp atomicAdd (order-independent => exact), last-block ticket
// finalize, self-resetting for graph replays.

#define PERC_THR 0.59275f
#define NBLK 148
#define NTHR 1024
#define NSEG 4608              // 32 KB segments: 3 * 50.3 MB / 32 KB

__device__ int g_cnt[576];              // per-row patch counts (int -> exact)
__device__ unsigned int g_ticket = 0;   // self-resetting -> deterministic replays

__device__ __forceinline__ float red4(float4 a) {
    return (a.x + a.y) + (a.z + a.w);
}

__global__ void __launch_bounds__(NTHR, 1)
perc_kernel(const float* __restrict__ x4,
            const float* __restrict__ x8,
            const float* __restrict__ x16,
            float* __restrict__ out) {
    __shared__ bool sh_last;

    const int tid  = threadIdx.x;
    const int lane = tid & 31;
    const int seg  = blockIdx.x * 32 + (tid >> 5);   // one 32 KB segment per warp

    if (seg < NSEG) {
        // Segment -> tensor + base. 32 KB = 2048 float4; row = 256 KB = 8 segs;
        // global row id = seg >> 3 (tensor boundaries align: 1536>>3 = 192).
        const float4* p;
        int tcase;
        if (seg < 1536)      { p = (const float4*)x4  + (size_t)seg * 2048;          tcase = 0; }
        else if (seg < 3072) { p = (const float4*)x8  + (size_t)(seg - 1536) * 2048; tcase = 1; }
        else                 { p = (const float4*)x16 + (size_t)(seg - 3072) * 2048; tcase = 2; }
        p += lane;

        int cnt = 0;
        // 8 batches of 8 coalesced warp-loads (batch = 256 float4 = 4 KB/warp
        // in flight), single buffer, runtime loop -- the R9 issue pattern.
#pragma unroll 1
        for (int i = 0; i < 8; i++) {
            float4 v[8];
#pragma unroll
            for (int j = 0; j < 8; j++)
                v[j] = p[i * 256 + j * 32];

            float a[8];
#pragma unroll
            for (int j = 0; j < 8; j++)
                a[j] = red4(v[j]);

            if (tcase == 0) {
                // x4: patch = 4 lanes
#pragma unroll
                for (int j = 0; j < 8; j++) {
                    a[j] += __shfl_xor_sync(0xffffffffu, a[j], 1);
                    a[j] += __shfl_xor_sync(0xffffffffu, a[j], 2);
                }
                if ((lane & 3) == 0) {
#pragma unroll
                    for (int j = 0; j < 8; j++)
                        cnt += (a[j] * 0.0625f >= PERC_THR) ? 1 : 0;
                }
            } else if (tcase == 1) {
                // x8: patch = 16 lanes
#pragma unroll
                for (int j = 0; j < 8; j++) {
#pragma unroll
                    for (int m = 1; m <= 8; m <<= 1)
                        a[j] += __shfl_xor_sync(0xffffffffu, a[j], m);
                }
                if ((lane & 15) == 0) {
#pragma unroll
                    for (int j = 0; j < 8; j++)
                        cnt += (a[j] * 0.015625f >= PERC_THR) ? 1 : 0;
                }
            } else {
                // x16: patch = 2 consecutive warp-loads -> 4 patches/batch
                float b[4];
#pragma unroll
                for (int j = 0; j < 4; j++)
                    b[j] = a[2 * j] + a[2 * j + 1];
#pragma unroll
                for (int j = 0; j < 4; j++) {
#pragma unroll
                    for (int m = 1; m <= 16; m <<= 1)
                        b[j] += __shfl_xor_sync(0xffffffffu, b[j], m);
                }
                if (lane == 0) {
#pragma unroll
                    for (int j = 0; j < 4; j++)
                        cnt += (b[j] * 0.00390625f >= PERC_THR) ? 1 : 0;
                }
            }
        }

        // Warp total -> one integer atomic per segment (order-independent, exact)
        cnt = __reduce_add_sync(0xffffffffu, cnt);
        if (lane == 0) atomicAdd(&g_cnt[seg >> 3], cnt);
    }

    // ---- last-block finalize (threadfence-reduction ticket pattern) ----
    __syncthreads();
    if (tid == 0) {
        __threadfence();                       // publish this block's atomics
        unsigned int t = atomicAdd(&g_ticket, 1);
        sh_last = (t == NBLK - 1);
    }
    __syncthreads();
    if (sh_last) {
        for (int t = tid; t < 576; t += NTHR) {
            int c = g_cnt[t];
            const float invP = (t < 192) ? (1.0f / 4096.0f)
                             : (t < 384) ? (1.0f / 1024.0f)
                                         : (1.0f / 256.0f);
            out[t] = (float)c * invP;
            g_cnt[t] = 0;                      // reset for next graph replay
        }
        if (tid == 0) g_ticket = 0;
    }
}

extern "C" void kernel_launch(void* const* d_in, const int* in_sizes, int n_in,
                              void* d_out, int out_size) {
    const float* x4  = (const float*)d_in[0];
    const float* x8  = (const float*)d_in[1];
    const float* x16 = (const float*)d_in[2];
    float* out = (float*)d_out;

    perc_kernel<<<NBLK, NTHR>>>(x4, x8, x16, out);
}